// round 6
// baseline (speedup 1.0000x reference)
#include <cuda_runtime.h>
#include <cstdint>

#define HD    256
#define OUTD  64
#define BSZ   64
#define NP    64
#define TT    128
#define MROWS (BSZ*NP)
#define M_U   (TT*BSZ)

__device__ float g_x[MROWS*HD];
__device__ float g_h[MROWS*HD];
__device__ float g_a[MROWS*HD];
__device__ float g_uproj[M_U*HD];   // u@W_ih^T + b_ih
__device__ uint2 g_keys[257];
__device__ float g_logdet;

// ---------------- Threefry-2x32 (JAX partitionable convention) ----------------
__device__ __forceinline__ void tf_block(uint32_t k0, uint32_t k1,
                                         uint32_t x0, uint32_t x1,
                                         uint32_t &o0, uint32_t &o1) {
    uint32_t ks2 = k0 ^ k1 ^ 0x1BD11BDAu;
    x0 += k0; x1 += k1;
#define TFR(r) { x0 += x1; x1 = (x1 << (r)) | (x1 >> (32 - (r))); x1 ^= x0; }
    TFR(13) TFR(15) TFR(26) TFR(6)
    x0 += k1;  x1 += ks2 + 1u;
    TFR(17) TFR(29) TFR(16) TFR(24)
    x0 += ks2; x1 += k0 + 2u;
    TFR(13) TFR(15) TFR(26) TFR(6)
    x0 += k0;  x1 += k1 + 3u;
    TFR(17) TFR(29) TFR(16) TFR(24)
    x0 += k1;  x1 += ks2 + 4u;
    TFR(13) TFR(15) TFR(26) TFR(6)
    x0 += ks2; x1 += k0 + 5u;
#undef TFR
    o0 = x0; o1 = x1;
}

__device__ __forceinline__ uint32_t tf_bits(uint2 k, uint32_t i) {
    uint32_t a, b;
    tf_block(k.x, k.y, 0u, i, a, b);
    return a ^ b;
}

// ---------------- XLA-matched elementwise ops ----------------
__device__ __forceinline__ float xla_erfinv(float x) {
    float w = -log1pf(-x * x);
    float p;
    if (w < 5.0f) {
        w = w - 2.5f;
        p = 2.81022636e-08f;
        p = fmaf(p, w, 3.43273939e-07f);
        p = fmaf(p, w, -3.5233877e-06f);
        p = fmaf(p, w, -4.39150654e-06f);
        p = fmaf(p, w, 0.00021858087f);
        p = fmaf(p, w, -0.00125372503f);
        p = fmaf(p, w, -0.00417768164f);
        p = fmaf(p, w, 0.246640727f);
        p = fmaf(p, w, 1.50140941f);
    } else {
        w = sqrtf(w) - 3.0f;
        p = -0.000200214257f;
        p = fmaf(p, w, 0.000100950558f);
        p = fmaf(p, w, 0.00134934322f);
        p = fmaf(p, w, -0.00367342844f);
        p = fmaf(p, w, 0.00573950773f);
        p = fmaf(p, w, -0.0076224613f);
        p = fmaf(p, w, 0.00943887047f);
        p = fmaf(p, w, 1.00167406f);
        p = fmaf(p, w, 2.83297682f);
    }
    return p * x;
}

__device__ __forceinline__ float bits_to_normal(uint32_t bits) {
    const float lo = -0.99999994f;
    float f = __uint_as_float((bits >> 9) | 0x3f800000u) - 1.0f;
    float u = __fadd_rn(__fmul_rn(f, 2.0f), lo);
    u = fmaxf(lo, u);
    return 1.4142135623730951f * xla_erfinv(u);
}

__device__ __forceinline__ float bits_to_gumbel(uint32_t bits) {
    const float tiny = 1.17549435e-38f;
    float f = __uint_as_float((bits >> 9) | 0x3f800000u) - 1.0f;
    float u = fmaxf(tiny, __fadd_rn(f, tiny));
    return -logf(-logf(u));
}

__device__ __forceinline__ float xla_tanh(float x) {
    if (fabsf(x) < 0.0004f) return x;
    float xc = fminf(fmaxf(x, -7.90531110763549805f), 7.90531110763549805f);
    float x2 = __fmul_rn(xc, xc);
    float p = -2.76076847742355e-16f;
    p = fmaf(p, x2, 2.00018790482477e-13f);
    p = fmaf(p, x2, -8.60467152213735e-11f);
    p = fmaf(p, x2, 5.12229709037114e-08f);
    p = fmaf(p, x2, 1.48572235717979e-05f);
    p = fmaf(p, x2, 6.37261928875436e-04f);
    p = fmaf(p, x2, 4.89352455891786e-03f);
    p = __fmul_rn(p, xc);
    float q = 1.19825839466702e-06f;
    q = fmaf(q, x2, 1.18534705686654e-04f);
    q = fmaf(q, x2, 2.26843463243900e-03f);
    q = fmaf(q, x2, 4.89352518554385e-03f);
    return __fdiv_rn(p, q);
}

// ---------------- Prologue ----------------
__global__ __launch_bounds__(256) void k_keys(const float* __restrict__ sy) {
    int j = threadIdx.x;
    uint32_t a0, a1;
    tf_block(0u, 42u, 0u, 1u, a0, a1);           // keyA = fold_in(key(42), 1)
    uint32_t s0, s1;
    tf_block(a0, a1, 0u, (uint32_t)j, s0, s1);   // split(keyA, 256)[j]
    g_keys[1 + j] = make_uint2(s0, s1);
    if (j == 0) {
        uint32_t b0, b1;
        tf_block(0u, 42u, 0u, 0u, b0, b1);       // fold_in(key(42), 0)
        g_keys[0] = make_uint2(b0, b1);
        float s = 0.0f;
        for (int o = 0; o < OUTD; o++) s += logf(sy[o]);
        g_logdet = 0.5f * s + 32.0f * 1.8378770664093453f;
    }
}

__global__ __launch_bounds__(256) void k_x0() {
    uint32_t i = blockIdx.x * 256u + threadIdx.x;
    uint2 key = g_keys[0];
    g_x[i] = bits_to_normal(tf_bits(key, i));
}

// ================= 128x64-tile GEMM cores (128 threads, 8x8/thread) =================
// As[buf][k][row(128)+pad], Bs[buf][k][col(64)+pad]; per-element k order preserved.

#define GEMM_PROLOG(APTR_EXPR, BPTR_NT)                                          \
    __shared__ float As[2][16][132];                                             \
    __shared__ float Bs[2][16][68];                                              \
    int tid = threadIdx.x;                                                       \
    int tx = tid & 7, ty = tid >> 3;     /* tx: 8 N-groups, ty: 16 M-groups */   \
    int row0 = blockIdx.x * 128, col0 = blockIdx.y * 64;                         \
    const float* Aptr = (APTR_EXPR);     /* row-major, row = row0+tid */         \
    float4 ar0, ar1, ar2, ar3, br0, br1;                                         \
    float acc[8][8] = {};

// NT B loader: B row-major [col][k]; thread (bcol=tid&63, bkh=tid>>6) loads 8 k.
#define LOAD_PANEL_NT(p)                                                         \
    ar0 = *(const float4*)(Aptr + (p)*16 + 0);                                   \
    ar1 = *(const float4*)(Aptr + (p)*16 + 4);                                   \
    ar2 = *(const float4*)(Aptr + (p)*16 + 8);                                   \
    ar3 = *(const float4*)(Aptr + (p)*16 + 12);                                  \
    br0 = *(const float4*)(Bptr + (p)*16 + 0);                                   \
    br1 = *(const float4*)(Bptr + (p)*16 + 4);

#define STORE_PANEL_NT(buf)                                                      \
    As[buf][0][tid]=ar0.x;  As[buf][1][tid]=ar0.y;  As[buf][2][tid]=ar0.z;  As[buf][3][tid]=ar0.w;  \
    As[buf][4][tid]=ar1.x;  As[buf][5][tid]=ar1.y;  As[buf][6][tid]=ar1.z;  As[buf][7][tid]=ar1.w;  \
    As[buf][8][tid]=ar2.x;  As[buf][9][tid]=ar2.y;  As[buf][10][tid]=ar2.z; As[buf][11][tid]=ar2.w; \
    As[buf][12][tid]=ar3.x; As[buf][13][tid]=ar3.y; As[buf][14][tid]=ar3.z; As[buf][15][tid]=ar3.w; \
    Bs[buf][bkh*8+0][bcol]=br0.x; Bs[buf][bkh*8+1][bcol]=br0.y;                  \
    Bs[buf][bkh*8+2][bcol]=br0.z; Bs[buf][bkh*8+3][bcol]=br0.w;                  \
    Bs[buf][bkh*8+4][bcol]=br1.x; Bs[buf][bkh*8+5][bcol]=br1.y;                  \
    Bs[buf][bkh*8+6][bcol]=br1.z; Bs[buf][bkh*8+7][bcol]=br1.w;

// NN B loader: B row-major [k][col-global]; thread loads 2 float4s of a 16x16-f4 panel.
#define LOAD_PANEL_NN(p)                                                         \
    ar0 = *(const float4*)(Aptr + (p)*16 + 0);                                   \
    ar1 = *(const float4*)(Aptr + (p)*16 + 4);                                   \
    ar2 = *(const float4*)(Aptr + (p)*16 + 8);                                   \
    ar3 = *(const float4*)(Aptr + (p)*16 + 12);                                  \
    br0 = *(const float4*)(BptrNN + ((size_t)((p)*16 + bk0)) * (BLD) + bc0*4);   \
    br1 = *(const float4*)(BptrNN + ((size_t)((p)*16 + bk1)) * (BLD) + bc1*4);

#define STORE_PANEL_NN(buf)                                                      \
    As[buf][0][tid]=ar0.x;  As[buf][1][tid]=ar0.y;  As[buf][2][tid]=ar0.z;  As[buf][3][tid]=ar0.w;  \
    As[buf][4][tid]=ar1.x;  As[buf][5][tid]=ar1.y;  As[buf][6][tid]=ar1.z;  As[buf][7][tid]=ar1.w;  \
    As[buf][8][tid]=ar2.x;  As[buf][9][tid]=ar2.y;  As[buf][10][tid]=ar2.z; As[buf][11][tid]=ar2.w; \
    As[buf][12][tid]=ar3.x; As[buf][13][tid]=ar3.y; As[buf][14][tid]=ar3.z; As[buf][15][tid]=ar3.w; \
    *(float4*)&Bs[buf][bk0][bc0*4] = br0;                                        \
    *(float4*)&Bs[buf][bk1][bc1*4] = br1;

#define COMPUTE_PANEL(buf)                                                       \
    _Pragma("unroll")                                                            \
    for (int kk = 0; kk < 16; kk++) {                                            \
        float4 a40 = *(const float4*)&As[buf][kk][ty*8];                         \
        float4 a41 = *(const float4*)&As[buf][kk][ty*8+4];                       \
        float4 b40 = *(const float4*)&Bs[buf][kk][tx*8];                         \
        float4 b41 = *(const float4*)&Bs[buf][kk][tx*8+4];                       \
        float a[8] = {a40.x,a40.y,a40.z,a40.w,a41.x,a41.y,a41.z,a41.w};          \
        float b[8] = {b40.x,b40.y,b40.z,b40.w,b41.x,b41.y,b41.z,b41.w};          \
        _Pragma("unroll")                                                        \
        for (int i = 0; i < 8; i++)                                              \
            _Pragma("unroll")                                                    \
            for (int j = 0; j < 8; j++)                                          \
                acc[i][j] = fmaf(a[i], b[j], acc[i][j]);                         \
    }

#define GEMM_MAIN_NT()                                                           \
    LOAD_PANEL_NT(0)                                                             \
    STORE_PANEL_NT(0)                                                            \
    __syncthreads();                                                             \
    _Pragma("unroll 1")                                                          \
    for (int p = 0; p < 16; p++) {                                               \
        if (p < 15) { LOAD_PANEL_NT(p + 1) }                                     \
        COMPUTE_PANEL(p & 1)                                                     \
        if (p < 15) { STORE_PANEL_NT((p + 1) & 1) __syncthreads(); }             \
    }

#define GEMM_MAIN_NN()                                                           \
    LOAD_PANEL_NN(0)                                                             \
    STORE_PANEL_NN(0)                                                            \
    __syncthreads();                                                             \
    _Pragma("unroll 1")                                                          \
    for (int p = 0; p < 16; p++) {                                               \
        if (p < 15) { LOAD_PANEL_NN(p + 1) }                                     \
        COMPUTE_PANEL(p & 1)                                                     \
        if (p < 15) { STORE_PANEL_NN((p + 1) & 1) __syncthreads(); }             \
    }

// uproj = u @ W_ih^T + b_ih   (M=8192, NT)
__global__ __launch_bounds__(128) void k_uproj(const float* __restrict__ u,
                                               const float* __restrict__ Wih,
                                               const float* __restrict__ bih) {
    GEMM_PROLOG(&u[(size_t)(blockIdx.x * 128 + threadIdx.x) * HD], )
    int bcol = tid & 63, bkh = tid >> 6;
    const float* Bptr = &Wih[(size_t)(col0 + bcol) * HD + bkh * 8];
    GEMM_MAIN_NT()
#pragma unroll
    for (int i = 0; i < 8; i++) {
        int r = row0 + ty*8 + i;
#pragma unroll
        for (int jq = 0; jq < 2; jq++) {
            float4 v;
            int c = col0 + tx*8 + jq*4;
            v.x = __fadd_rn(acc[i][jq*4+0], bih[c+0]);
            v.y = __fadd_rn(acc[i][jq*4+1], bih[c+1]);
            v.z = __fadd_rn(acc[i][jq*4+2], bih[c+2]);
            v.w = __fadd_rn(acc[i][jq*4+3], bih[c+3]);
            *(float4*)&g_uproj[(size_t)r * HD + c] = v;
        }
    }
}

// h = tanh(((uWih+bih) + xWhh) + bhh) + normal * sqrt(sx)   (M=4096, NT)
__global__ __launch_bounds__(128) void k_rnn(const float* __restrict__ Whh,
                                             const float* __restrict__ bhh,
                                             const float* __restrict__ sx,
                                             int t) {
    GEMM_PROLOG(&g_x[(size_t)(blockIdx.x * 128 + threadIdx.x) * HD], )
    int bcol = tid & 63, bkh = tid >> 6;
    const float* Bptr = &Whh[(size_t)(col0 + bcol) * HD + bkh * 8];
    GEMM_MAIN_NT()
    uint2 nkey = g_keys[1 + 2*t];
#pragma unroll
    for (int i = 0; i < 8; i++) {
        int r = row0 + ty*8 + i;
        int b = r >> 6;
        const float* uprow = &g_uproj[(size_t)(t * BSZ + b) * HD];
#pragma unroll
        for (int jq = 0; jq < 2; jq++) {
            int c0 = col0 + tx*8 + jq*4;
            float4 v;
            float* vp = &v.x;
#pragma unroll
            for (int j = 0; j < 4; j++) {
                int c = c0 + j;
                float pre = __fadd_rn(__fadd_rn(uprow[c], acc[i][jq*4+j]), bhh[c]);
                float tv = xla_tanh(pre);
                uint32_t idx = (uint32_t)r * HD + (uint32_t)c;
                float nz = __fmul_rn(bits_to_normal(tf_bits(nkey, idx)), sqrtf(sx[c]));
                vp[j] = __fadd_rn(tv, nz);
            }
            *(float4*)&g_h[(size_t)r * HD + c0] = v;
        }
    }
}

// a = relu(h@W1 + b1)   (M=4096, NN)
__global__ __launch_bounds__(128) void k_ffn1(const float* __restrict__ W1,
                                              const float* __restrict__ b1) {
    GEMM_PROLOG(&g_h[(size_t)(blockIdx.x * 128 + threadIdx.x) * HD], )
    const float* BptrNN = W1 + col0;          // [k][HD] row-major, col offset col0
    const int BLD = HD;
    int bk0 = tid >> 4, bc0 = tid & 15;                 // f4 index tid
    int bk1 = (tid + 128) >> 4, bc1 = (tid + 128) & 15; // f4 index tid+128
    GEMM_MAIN_NN()
#pragma unroll
    for (int i = 0; i < 8; i++) {
        int r = row0 + ty*8 + i;
#pragma unroll
        for (int jq = 0; jq < 2; jq++) {
            int c = col0 + tx*8 + jq*4;
            float4 v;
            v.x = fmaxf(__fadd_rn(acc[i][jq*4+0], b1[c+0]), 0.0f);
            v.y = fmaxf(__fadd_rn(acc[i][jq*4+1], b1[c+1]), 0.0f);
            v.z = fmaxf(__fadd_rn(acc[i][jq*4+2], b1[c+2]), 0.0f);
            v.w = fmaxf(__fadd_rn(acc[i][jq*4+3], b1[c+3]), 0.0f);
            *(float4*)&g_a[(size_t)r * HD + c] = v;
        }
    }
}

// Fused: yhat = a@W2 + b2 (one block = one batch) -> out + smem;
// then lp (XLA tree), log_softmax, gumbel-argmax, particle gather.
__global__ __launch_bounds__(256) void k_out_resample(
        const float* __restrict__ W2, const float* __restrict__ b2,
        const float* __restrict__ y,  const float* __restrict__ sy,
        float* __restrict__ out, int t) {
    __shared__ float As[16][68];
    __shared__ float Bs[16][68];
    __shared__ float sm_out[64][68];
    __shared__ float lp_s[64];
    __shared__ float logw_s[64];
    __shared__ int   idx_s[64];
    int tid = threadIdx.x, tx = tid & 15, ty = tid >> 4;
    int b = blockIdx.x;
    int row0 = b * 64;
    int lr = tid >> 2, lc4 = (tid & 3) * 4;
    int lr2 = tid >> 4, lc2 = (tid & 15) * 4;
    const float* Aptr = &g_a[(size_t)(row0 + lr) * HD + lc4];
    const float* Bptr = &W2[(size_t)lr2 * OUTD + lc2];
    float4 a_reg = *(const float4*)Aptr;
    float4 b_reg = *(const float4*)Bptr;
    float acc[4][4] = {};
#pragma unroll 1
    for (int p = 0; p < 16; p++) {
        As[lc4+0][lr] = a_reg.x; As[lc4+1][lr] = a_reg.y;
        As[lc4+2][lr] = a_reg.z; As[lc4+3][lr] = a_reg.w;
        *(float4*)&Bs[lr2][lc2] = b_reg;
        __syncthreads();
        if (p < 15) {
            a_reg = *(const float4*)(Aptr + (p + 1) * 16);
            b_reg = *(const float4*)(Bptr + (size_t)(p + 1) * 16 * OUTD);
        }
#pragma unroll
        for (int kk = 0; kk < 16; kk++) {
            float4 a4 = *(const float4*)&As[kk][ty*4];
            float4 b4 = *(const float4*)&Bs[kk][tx*4];
            float a[4] = {a4.x, a4.y, a4.z, a4.w};
            float bb[4] = {b4.x, b4.y, b4.z, b4.w};
#pragma unroll
            for (int i = 0; i < 4; i++)
#pragma unroll
                for (int j = 0; j < 4; j++)
                    acc[i][j] = fmaf(a[i], bb[j], acc[i][j]);
        }
        __syncthreads();
    }
#pragma unroll
    for (int i = 0; i < 4; i++) {
        int rl = ty*4 + i;
#pragma unroll
        for (int j = 0; j < 4; j++) {
            int c = tx*4 + j;
            float v = __fadd_rn(acc[i][j], b2[c]);
            out[(size_t)t * (MROWS*OUTD) + (size_t)(row0 + rl) * OUTD + c] = v;
            sm_out[rl][c] = v;
        }
    }
    __syncthreads();
    int w = tid >> 5, lane = tid & 31;
    {
        const float* yrow = &y[(size_t)(t * BSZ + b) * OUTD];
        float y0 = yrow[lane], y1 = yrow[lane + 32];
        float s0y = sy[lane], s1y = sy[lane + 32];
        float logdet = g_logdet;
        for (int s = w; s < 64; s += 8) {
            float d0 = __fsub_rn(sm_out[s][lane],      y0);
            float d1 = __fsub_rn(sm_out[s][lane + 32], y1);
            float t0 = __fdiv_rn(__fmul_rn(d0, d0), s0y);
            float t1 = __fdiv_rn(__fmul_rn(d1, d1), s1y);
            float ssum = __fadd_rn(t0, t1);
#pragma unroll
            for (int off = 16; off >= 1; off >>= 1)
                ssum = __fadd_rn(ssum, __shfl_down_sync(0xffffffffu, ssum, off));
            if (lane == 0)
                lp_s[s] = __fsub_rn(__fmul_rn(-0.5f, ssum), logdet);
        }
    }
    __syncthreads();
    if (tid < 32) {
        float v0 = lp_s[tid];
        float v1 = lp_s[tid + 32];
        float m = fmaxf(v0, v1);
#pragma unroll
        for (int off = 16; off >= 1; off >>= 1)
            m = fmaxf(m, __shfl_xor_sync(0xffffffffu, m, off));
        float sh0 = __fsub_rn(v0, m);
        float sh1 = __fsub_rn(v1, m);
        float e = __fadd_rn(expf(sh0), expf(sh1));
#pragma unroll
        for (int off = 16; off >= 1; off >>= 1)
            e = __fadd_rn(e, __shfl_down_sync(0xffffffffu, e, off));
        float ls = logf(__shfl_sync(0xffffffffu, e, 0));
        logw_s[tid]      = __fsub_rn(sh0, ls);
        logw_s[tid + 32] = __fsub_rn(sh1, ls);
    }
    __syncthreads();
    uint2 gkey = g_keys[1 + 2*t + 1];
    for (int s = w; s < 64; s += 8) {
        uint32_t base = (uint32_t)s * 4096u + (uint32_t)b * 64u;
        float v0 = __fadd_rn(bits_to_gumbel(tf_bits(gkey, base + lane)),      logw_s[lane]);
        float v1 = __fadd_rn(bits_to_gumbel(tf_bits(gkey, base + 32 + lane)), logw_s[lane + 32]);
        float bv; int bi;
        if (v1 > v0) { bv = v1; bi = lane + 32; } else { bv = v0; bi = lane; }
#pragma unroll
        for (int off = 16; off >= 1; off >>= 1) {
            float ov = __shfl_xor_sync(0xffffffffu, bv, off);
            int   oi = __shfl_xor_sync(0xffffffffu, bi, off);
            if (ov > bv || (ov == bv && oi < bi)) { bv = ov; bi = oi; }
        }
        if (lane == 0) idx_s[s] = bi;
    }
    __syncthreads();
    const float4* hsrc = (const float4*)g_h;
    float4* xdst = (float4*)g_x;
    for (int e = tid; e < 64*64; e += 256) {
        int s = e >> 6, c4 = e & 63;
        xdst[(size_t)(b*64 + s) * 64 + c4] = hsrc[(size_t)(b*64 + idx_s[s]) * 64 + c4];
    }
}

extern "C" void kernel_launch(void* const* d_in, const int* in_sizes, int n_in,
                              void* d_out, int out_size) {
    (void)in_sizes; (void)n_in; (void)out_size;
    const float* u   = (const float*)d_in[0];
    const float* y   = (const float*)d_in[1];
    const float* Wih = (const float*)d_in[2];
    const float* Whh = (const float*)d_in[3];
    const float* bih = (const float*)d_in[4];
    const float* bhh = (const float*)d_in[5];
    const float* W1  = (const float*)d_in[6];
    const float* b1  = (const float*)d_in[7];
    const float* W2  = (const float*)d_in[8];
    const float* b2  = (const float*)d_in[9];
    const float* sx  = (const float*)d_in[10];
    const float* sy  = (const float*)d_in[11];
    float* out = (float*)d_out;

    k_keys<<<1, 256>>>(sy);
    k_x0<<<4096, 256>>>();
    k_uproj<<<dim3(64, 4), 128>>>(u, Wih, bih);
    for (int t = 0; t < TT; t++) {
        k_rnn<<<dim3(32, 4), 128>>>(Whh, bhh, sx, t);
        k_ffn1<<<dim3(32, 4), 128>>>(W1, b1);
        k_out_resample<<<64, 256>>>(W2, b2, y, sy, out, t);
    }
}